// round 10
// baseline (speedup 1.0000x reference)
#include <cuda_runtime.h>
#include <cuda_fp16.h>
#include <cstddef>

// ---------------------------------------------------------------------------
// GMM (MoNet) graph conv — 3-kernel pipeline:
//   T1:   y1 = x*W1, fp16 out (unpadded 192B rows); W1 staged fp16 in smem,
//         inner loop = 2x LDS.128 + 16 FFMA2 per f (balanced smem/fma)
//   G1T2: h[n] = gather(y1) (smem only), then per-node GEMM y2 = h*W2,
//         y2 stored as padded 128B rows [8 chunks][{k0,k1,k2,pad} half2]
//   G2:   out[n] = gather(y2), 1 LDG.128 per edge-lane (1 line/node)
// ---------------------------------------------------------------------------

#define MAXN 131072
__device__ __half g_y1[MAXN * 96];   // [N][3][32]  unpadded, 192B rows
__device__ __half g_y2[MAXN * 64];   // [N][8 chunks][8 halves], 128B rows

typedef unsigned long long ull;

__device__ __forceinline__ ull pk2(float x, float y) {
    ull r; asm("mov.b64 %0, {%1,%2};" : "=l"(r) : "f"(x), "f"(y)); return r;
}
__device__ __forceinline__ void upk2(ull v, float& x, float& y) {
    asm("mov.b64 {%0,%1}, %2;" : "=f"(x), "=f"(y) : "l"(v));
}
__device__ __forceinline__ void ffma2(ull& d, ull a, ull b) {
    asm("fma.rn.f32x2 %0, %1, %2, %0;" : "+l"(d) : "l"(a), "l"(b));
}

// ======================= T1: dense transform (ffma2 GEMM) ==================
// MT=64, 192 thr = 12(tx: 4 consecutive n-pairs) x 16(ty: 4 m-rows).
// Per f: 1x LDS.128 Xs + 1x LDS.128 Wh(fp16) + 16 FFMA2.
__global__ void __launch_bounds__(192, 6)
t1_kernel(const float* __restrict__ X, const float* __restrict__ W,
          uint4* __restrict__ Y,           // y1 as 16B chunks (12 per row)
          int n_nodes)
{
    constexpr int KD = 64, MT = 64, XSTR = 68;   // XSTR*4 % 16 == 0

    __shared__ float   Xs[KD * XSTR];            // 17408 B
    __shared__ __half2 Wh[KD * 48];              // 12288 B  [f][48 pairs]

    const int tid = threadIdx.x;
    const int mt0 = blockIdx.x * MT;

    // Stage W1 -> fp16 pairs: Wh[f*48 + k*16 + hp] = (W[k][f][2hp], W[k][f][2hp+1])
    for (int i = tid; i < KD * 48; i += 192) {
        const int f = i / 48, j = i % 48;
        const int k = j / 16, hp = j % 16;
        const float* wr = W + ((size_t)k * KD + f) * 32 + 2 * hp;
        Wh[i] = __floats2half2_rn(wr[0], wr[1]);
    }
    // Stage X transposed: Xs[f*XSTR + m] = X[mt0+m][f]
    for (int i = tid; i < MT * KD; i += 192) {
        const int m = i / KD, f = i % KD;
        float v = 0.f;
        if (mt0 + m < n_nodes) v = X[(size_t)(mt0 + m) * KD + f];
        Xs[f * XSTR + m] = v;
    }
    __syncthreads();

    const int tx = tid % 12;               // owns pairs 4tx..4tx+3 (same k-block)
    const int ty = tid / 12;               // owns rows 4ty..4ty+3
    const int m0 = 4 * ty;
    const int j0 = 4 * tx;

    ull acc[4][4];                         // [m-row][n-pair]
    #pragma unroll
    for (int i = 0; i < 4; i++)
        #pragma unroll
        for (int s = 0; s < 4; s++) acc[i][s] = 0ull;

    for (int f = 0; f < KD; f++) {
        const float4 xv = *(const float4*)&Xs[f * XSTR + m0];
        ull xp[4];
        xp[0] = pk2(xv.x, xv.x);
        xp[1] = pk2(xv.y, xv.y);
        xp[2] = pk2(xv.z, xv.z);
        xp[3] = pk2(xv.w, xv.w);

        const uint4 wv = *(const uint4*)&Wh[f * 48 + j0];
        const float2 w0 = __half22float2(*(const __half2*)&wv.x);
        const float2 w1 = __half22float2(*(const __half2*)&wv.y);
        const float2 w2 = __half22float2(*(const __half2*)&wv.z);
        const float2 w3 = __half22float2(*(const __half2*)&wv.w);
        ull wp[4];
        wp[0] = pk2(w0.x, w0.y);
        wp[1] = pk2(w1.x, w1.y);
        wp[2] = pk2(w2.x, w2.y);
        wp[3] = pk2(w3.x, w3.y);

        #pragma unroll
        for (int s = 0; s < 4; s++)
            #pragma unroll
            for (int i = 0; i < 4; i++)
                ffma2(acc[i][s], xp[i], wp[s]);
    }

    // Store: 4 consecutive half2 pairs per m-row -> one STG.128
    #pragma unroll
    for (int i = 0; i < 4; i++) {
        const int m = mt0 + m0 + i;
        if (m >= n_nodes) break;
        __half2 hp[4];
        #pragma unroll
        for (int s = 0; s < 4; s++) {
            float v0, v1; upk2(acc[i][s], v0, v1);
            hp[s] = __floats2half2_rn(v0, v1);
        }
        // y1 row = 48 half2 = 12 uint4 chunks; chunk index = j0/4 = tx
        Y[(size_t)m * 12 + tx] = *(const uint4*)hp;
    }
}

// ============================== gaussians ==================================
#define LOAD_GAUSS_PARAMS()                                                   \
    const float m0_ = mu[0], m1_ = mu[1], m2_ = mu[2],                        \
                m3_ = mu[3], m4_ = mu[4], m5_ = mu[5];                        \
    float s_;                                                                 \
    s_ = sigma[0]; const float i0_ = 1.f/(s_*s_);                             \
    s_ = sigma[1]; const float i1_ = 1.f/(s_*s_);                             \
    s_ = sigma[2]; const float i2_ = 1.f/(s_*s_);                             \
    s_ = sigma[3]; const float i3_ = 1.f/(s_*s_);                             \
    s_ = sigma[4]; const float i4_ = 1.f/(s_*s_);                             \
    s_ = sigma[5]; const float i5_ = 1.f/(s_*s_);

#define GAUSS3(pv, g0, g1, g2) do {                                           \
    float dx_, dy_, q_;                                                       \
    dx_ = (pv).x - m0_; dy_ = (pv).y - m1_;                                   \
    q_ = dx_*dx_*i0_ + dy_*dy_*i1_; g0 = __expf(-0.5f * q_);                  \
    dx_ = (pv).x - m2_; dy_ = (pv).y - m3_;                                   \
    q_ = dx_*dx_*i2_ + dy_*dy_*i3_; g1 = __expf(-0.5f * q_);                  \
    dx_ = (pv).x - m4_; dy_ = (pv).y - m5_;                                   \
    q_ = dx_*dx_*i4_ + dy_*dy_*i5_; g2 = __expf(-0.5f * q_);                  \
} while (0)

// ============== G1 + T2 fused: gather -> h (smem) -> y2 = h*W2 =============
template<int NWARP, int GRP>
__global__ void __launch_bounds__(NWARP * 32)
g1t2_kernel(const int* __restrict__ row_ptr, const int* __restrict__ col_idx,
            const float2* __restrict__ p,
            const float* __restrict__ mu, const float* __restrict__ sigma,
            const uint2* __restrict__ y,      // y1: [N][24] uint2
            const float* __restrict__ W2,     // [3][32][16]
            unsigned* __restrict__ y2,        // [N][32] uint (128B rows)
            int n_nodes)
{
    constexpr int CAP = GRP * 16;
    __shared__ float4 stg[NWARP][CAP];
    __shared__ float  hbuf[NWARP][GRP][32];
    __shared__ ull    wp[24 * 33];            // W2 pairs, stride 33

    const int tid  = threadIdx.x;
    const int lane = tid & 31;
    const int wid  = tid >> 5;

    for (int i = tid; i < 24 * 32; i += NWARP * 32) {
        const int l = i / 32, f = i % 32;
        const int hp = l / 3, k = l % 3;
        const float* wrow = W2 + ((size_t)k * 32 + f) * 16 + 2 * hp;
        wp[l * 33 + f] = pk2(wrow[0], wrow[1]);
    }
    __syncthreads();

    const int base = (blockIdx.x * NWARP + wid) * GRP;
    if (base >= n_nodes) return;

    LOAD_GAUSS_PARAMS();

    const int ng   = min(GRP, n_nodes - base);
    const int e0   = row_ptr[base];
    const int ecnt = row_ptr[base + ng] - e0;
    const bool fast = (ecnt <= CAP);

    if (fast) {
        for (int j = lane; j < ecnt; j += 32) {
            const int e = e0 + j;
            const int c = col_idx[e];
            const float2 pv = __ldg(p + e);
            float g0, g1, g2; GAUSS3(pv, g0, g1, g2);
            stg[wid][j] = make_float4(g0, g1, g2, __int_as_float(c));
        }
    }
    __syncwarp();

    const int s  = lane >> 3;
    const int hl = lane & 7;

    #pragma unroll
    for (int pi = 0; pi < GRP / 4; pi++) {
        const int n = base + pi * 4 + s;
        const bool valid = (n < n_nodes);
        const int nc  = valid ? n : base;
        const int st  = __ldg(row_ptr + nc);
        const int deg = valid ? (__ldg(row_ptr + nc + 1) - st) : 0;

        ull a[3][2];
        #pragma unroll
        for (int k = 0; k < 3; k++) { a[k][0] = 0ull; a[k][1] = 0ull; }

        if (fast) {
            const float4* sd = &stg[wid][st - e0];
            const bool u16 = __all_sync(0xffffffffu, deg == 16);
            #define G1_BODY(J) do {                                           \
                const float4 ed = sd[(J)];                                    \
                const int c = __float_as_int(ed.w);                           \
                const uint2* yr = y + (size_t)c * 24 + hl;                    \
                const uint2 v0 = __ldg(yr);                                   \
                const uint2 v1 = __ldg(yr + 8);                               \
                const uint2 v2 = __ldg(yr + 16);                              \
                const float2 c00 = __half22float2(*(const __half2*)&v0.x);    \
                const float2 c01 = __half22float2(*(const __half2*)&v0.y);    \
                const float2 c10 = __half22float2(*(const __half2*)&v1.x);    \
                const float2 c11 = __half22float2(*(const __half2*)&v1.y);    \
                const float2 c20 = __half22float2(*(const __half2*)&v2.x);    \
                const float2 c21 = __half22float2(*(const __half2*)&v2.y);    \
                const ull w0 = pk2(ed.x, ed.x);                               \
                const ull w1 = pk2(ed.y, ed.y);                               \
                const ull w2 = pk2(ed.z, ed.z);                               \
                ffma2(a[0][0], w0, pk2(c00.x, c00.y));                        \
                ffma2(a[0][1], w0, pk2(c01.x, c01.y));                        \
                ffma2(a[1][0], w1, pk2(c10.x, c10.y));                        \
                ffma2(a[1][1], w1, pk2(c11.x, c11.y));                        \
                ffma2(a[2][0], w2, pk2(c20.x, c20.y));                        \
                ffma2(a[2][1], w2, pk2(c21.x, c21.y));                        \
            } while (0)
            if (u16) {
                #pragma unroll
                for (int j = 0; j < 16; j++) G1_BODY(j);
            } else {
                const int maxd = __reduce_max_sync(0xffffffffu, deg);
                for (int j = 0; j < maxd; j++)
                    if (j < deg) G1_BODY(j);
            }
            #undef G1_BODY
        } else {
            const int maxd = __reduce_max_sync(0xffffffffu, deg);
            for (int j = 0; j < maxd; j++) {
                if (j < deg) {
                    const int e = st + j;
                    const int c = __ldg(col_idx + e);
                    const float2 pv = __ldg(p + e);
                    float g0, g1, g2; GAUSS3(pv, g0, g1, g2);
                    const uint2* yr = y + (size_t)c * 24 + hl;
                    const uint2 v0 = __ldg(yr);
                    const uint2 v1 = __ldg(yr + 8);
                    const uint2 v2 = __ldg(yr + 16);
                    const float2 c00 = __half22float2(*(const __half2*)&v0.x);
                    const float2 c01 = __half22float2(*(const __half2*)&v0.y);
                    const float2 c10 = __half22float2(*(const __half2*)&v1.x);
                    const float2 c11 = __half22float2(*(const __half2*)&v1.y);
                    const float2 c20 = __half22float2(*(const __half2*)&v2.x);
                    const float2 c21 = __half22float2(*(const __half2*)&v2.y);
                    ffma2(a[0][0], pk2(g0, g0), pk2(c00.x, c00.y));
                    ffma2(a[0][1], pk2(g0, g0), pk2(c01.x, c01.y));
                    ffma2(a[1][0], pk2(g1, g1), pk2(c10.x, c10.y));
                    ffma2(a[1][1], pk2(g1, g1), pk2(c11.x, c11.y));
                    ffma2(a[2][0], pk2(g2, g2), pk2(c20.x, c20.y));
                    ffma2(a[2][1], pk2(g2, g2), pk2(c21.x, c21.y));
                }
            }
        }

        float p00, p01, p10, p11, q00, q01, q10, q11, r00, r01, r10, r11;
        upk2(a[0][0], p00, p01); upk2(a[0][1], p10, p11);
        upk2(a[1][0], q00, q01); upk2(a[1][1], q10, q11);
        upk2(a[2][0], r00, r01); upk2(a[2][1], r10, r11);
        float4 o;
        o.x = p00 + q00 + r00;
        o.y = p01 + q01 + r01;
        o.z = p10 + q10 + r10;
        o.w = p11 + q11 + r11;
        *(float4*)&hbuf[wid][pi * 4 + s][4 * hl] = o;
    }
    __syncwarp();

    // fused T2: y2[g] = h[g] * W2
    const int wl = (lane < 24) ? lane : 0;
    const ull* wcol = wp + wl * 33;

    ull acc[GRP];
    #pragma unroll
    for (int g = 0; g < GRP; g++) acc[g] = 0ull;

    #pragma unroll
    for (int fc = 0; fc < 8; fc++) {
        ull wr[4];
        #pragma unroll
        for (int f4 = 0; f4 < 4; f4++) wr[f4] = wcol[fc * 4 + f4];
        #pragma unroll
        for (int g = 0; g < GRP; g++) {
            const float4 hv = *(const float4*)&hbuf[wid][g][fc * 4];
            ffma2(acc[g], pk2(hv.x, hv.x), wr[0]);
            ffma2(acc[g], pk2(hv.y, hv.y), wr[1]);
            ffma2(acc[g], pk2(hv.z, hv.z), wr[2]);
            ffma2(acc[g], pk2(hv.w, hv.w), wr[3]);
        }
    }

    const int oidx = (lane / 3) * 4 + (lane % 3);
    #pragma unroll
    for (int g = 0; g < GRP; g++) {
        const int n = base + g;
        if (lane < 24 && n < n_nodes) {
            float lo, hi; upk2(acc[g], lo, hi);
            const __half2 hv = __floats2half2_rn(lo, hi);
            y2[(size_t)n * 32 + oidx] = *(const unsigned*)&hv;
        }
    }
}

// ---- G2: H=16, padded 128B rows; 8 lanes/node, 1x LDG.128 per edge --------
template<int NWARP, int GRP>
__global__ void __launch_bounds__(NWARP * 32)
gather_h16(const int* __restrict__ row_ptr, const int* __restrict__ col_idx,
           const float2* __restrict__ p,
           const float* __restrict__ mu, const float* __restrict__ sigma,
           const uint4* __restrict__ y,     // [N][8] 16B chunks
           float* __restrict__ out,         // [N][16] f32
           int n_nodes)
{
    constexpr int CAP = GRP * 16;
    __shared__ float4 stg[NWARP][CAP];

    const int lane = threadIdx.x & 31;
    const int wid  = threadIdx.x >> 5;
    const int s    = lane >> 3;
    const int hl   = lane & 7;
    const int base = (blockIdx.x * NWARP + wid) * GRP;
    if (base >= n_nodes) return;

    LOAD_GAUSS_PARAMS();

    const int ng   = min(GRP, n_nodes - base);
    const int e0   = row_ptr[base];
    const int ecnt = row_ptr[base + ng] - e0;
    const bool fast = (ecnt <= CAP);

    if (fast) {
        for (int j = lane; j < ecnt; j += 32) {
            const int e = e0 + j;
            const int c = col_idx[e];
            const float2 pv = __ldg(p + e);
            float g0, g1, g2; GAUSS3(pv, g0, g1, g2);
            stg[wid][j] = make_float4(g0, g1, g2, __int_as_float(c));
        }
    }
    __syncwarp();

    #pragma unroll
    for (int pi = 0; pi < GRP / 4; pi++) {
        const int n = base + pi * 4 + s;
        const bool valid = (n < n_nodes);
        const int nc  = valid ? n : base;
        const int st  = __ldg(row_ptr + nc);
        const int deg = valid ? (__ldg(row_ptr + nc + 1) - st) : 0;

        ull a0 = 0ull, a1 = 0ull, a2 = 0ull;

        if (fast) {
            const float4* sd = &stg[wid][st - e0];
            const bool u16 = __all_sync(0xffffffffu, deg == 16);
            #define G2_BODY(J) do {                                           \
                const float4 ed = sd[(J)];                                    \
                const int c = __float_as_int(ed.w);                           \
                const uint4 v = __ldg(y + (size_t)c * 8 + hl);                \
                const float2 f0 = __half22float2(*(const __half2*)&v.x);      \
                const float2 f1 = __half22float2(*(const __half2*)&v.y);      \
                const float2 f2 = __half22float2(*(const __half2*)&v.z);      \
                ffma2(a0, pk2(ed.x, ed.x), pk2(f0.x, f0.y));                  \
                ffma2(a1, pk2(ed.y, ed.y), pk2(f1.x, f1.y));                  \
                ffma2(a2, pk2(ed.z, ed.z), pk2(f2.x, f2.y));                  \
            } while (0)
            if (u16) {
                #pragma unroll
                for (int j = 0; j < 16; j++) G2_BODY(j);
            } else {
                const int maxd = __reduce_max_sync(0xffffffffu, deg);
                for (int j = 0; j < maxd; j++)
                    if (j < deg) G2_BODY(j);
            }
            #undef G2_BODY
        } else {
            const int maxd = __reduce_max_sync(0xffffffffu, deg);
            for (int j = 0; j < maxd; j++) {
                if (j < deg) {
                    const int e = st + j;
                    const int c = __ldg(col_idx + e);
                    const float2 pv = __ldg(p + e);
                    float g0, g1, g2; GAUSS3(pv, g0, g1, g2);
                    const uint4 v = __ldg(y + (size_t)c * 8 + hl);
                    const float2 f0 = __half22float2(*(const __half2*)&v.x);
                    const float2 f1 = __half22float2(*(const __half2*)&v.y);
                    const float2 f2 = __half22float2(*(const __half2*)&v.z);
                    ffma2(a0, pk2(g0, g0), pk2(f0.x, f0.y));
                    ffma2(a1, pk2(g1, g1), pk2(f1.x, f1.y));
                    ffma2(a2, pk2(g2, g2), pk2(f2.x, f2.y));
                }
            }
        }

        if (valid) {
            float x0, x1, y0v, y1v, z0, z1;
            upk2(a0, x0, x1); upk2(a1, y0v, y1v); upk2(a2, z0, z1);
            float2 o = make_float2(x0 + y0v + z0, x1 + y1v + z1);
            *(float2*)(out + (size_t)n * 16 + 2 * hl) = o;
        }
    }
}

// =============================== launch ====================================
extern "C" void kernel_launch(void* const* d_in, const int* in_sizes, int n_in,
                              void* d_out, int out_size)
{
    const int*    row_ptr = (const int*)d_in[0];    // int32 (JAX x64 disabled)
    const int*    col_idx = (const int*)d_in[1];
    const float*  x       = (const float*)d_in[2];
    const float2* p       = (const float2*)d_in[3];
    const float*  mu      = (const float*)d_in[4];
    const float*  sg      = (const float*)d_in[5];
    const float*  W1      = (const float*)d_in[6];
    const float*  W2      = (const float*)d_in[7];

    const int n_nodes = in_sizes[0] - 1;

    void *y1p, *y2p;
    cudaGetSymbolAddress(&y1p, g_y1);
    cudaGetSymbolAddress(&y2p, g_y2);

    constexpr int NWARP = 8;
    constexpr int GRP   = 8;
    const int gblocks = (n_nodes + NWARP * GRP - 1) / (NWARP * GRP);
    const int tblocks = (n_nodes + 63) / 64;

    // T1: y1 = x * W1  (fp16 unpadded rows, W staged fp16, LDS.128 inner loop)
    t1_kernel<<<tblocks, 192>>>(x, W1, (uint4*)y1p, n_nodes);
    // G1+T2: h = gather(y1) in smem; y2 = h*W2 (padded 128B rows)
    g1t2_kernel<NWARP, GRP><<<gblocks, NWARP * 32>>>(
        row_ptr, col_idx, p, mu, sg, (const uint2*)y1p, W2,
        (unsigned*)y2p, n_nodes);
    // G2: out = gather(y2)  (8 lanes/node, 1x LDG.128/edge)
    gather_h16<NWARP, GRP><<<gblocks, NWARP * 32>>>(
        row_ptr, col_idx, p, mu, sg, (const uint4*)y2p, (float*)d_out, n_nodes);
}

// round 11
// speedup vs baseline: 1.1660x; 1.1660x over previous
#include <cuda_runtime.h>
#include <cuda_fp16.h>
#include <cstddef>
#include <cstdint>

// ---------------------------------------------------------------------------
// GMM (MoNet) graph conv — 3-kernel pipeline:
//   T1:   y1 = x*W1 via mma.sync.m16n8k16 (fp16 in, f32 acc, fp16 out),
//         unpadded 192B y1 rows ([3][16] half2)
//   G1T2: h[n] = gather(y1) (smem only), then per-node GEMM y2 = h*W2,
//         y2 stored as padded 128B rows [8 chunks][{k0,k1,k2,pad} half2]
//   G2:   out[n] = gather(y2), 1 LDG.128 per edge-lane (1 line/node)
// ---------------------------------------------------------------------------

#define MAXN 131072
__device__ __half g_y1[MAXN * 96];   // [N][3][32]  unpadded, 192B rows
__device__ __half g_y2[MAXN * 64];   // [N][8 chunks][8 halves], 128B rows

typedef unsigned long long ull;

__device__ __forceinline__ ull pk2(float x, float y) {
    ull r; asm("mov.b64 %0, {%1,%2};" : "=l"(r) : "f"(x), "f"(y)); return r;
}
__device__ __forceinline__ void upk2(ull v, float& x, float& y) {
    asm("mov.b64 {%0,%1}, %2;" : "=f"(x), "=f"(y) : "l"(v));
}
__device__ __forceinline__ void ffma2(ull& d, ull a, ull b) {
    asm("fma.rn.f32x2 %0, %1, %2, %0;" : "+l"(d) : "l"(a), "l"(b));
}

__device__ __forceinline__ void ldsm_x4(uint32_t& r0, uint32_t& r1,
                                        uint32_t& r2, uint32_t& r3, uint32_t a) {
    asm volatile("ldmatrix.sync.aligned.m8n8.x4.shared.b16 {%0,%1,%2,%3}, [%4];"
                 : "=r"(r0), "=r"(r1), "=r"(r2), "=r"(r3) : "r"(a));
}
__device__ __forceinline__ void ldsm_x2_t(uint32_t& r0, uint32_t& r1, uint32_t a) {
    asm volatile("ldmatrix.sync.aligned.m8n8.x2.trans.shared.b16 {%0,%1}, [%2];"
                 : "=r"(r0), "=r"(r1) : "r"(a));
}
__device__ __forceinline__ void mma16816(float* c,
    uint32_t a0, uint32_t a1, uint32_t a2, uint32_t a3, uint32_t b0, uint32_t b1) {
    asm volatile(
        "mma.sync.aligned.m16n8k16.row.col.f32.f16.f16.f32 "
        "{%0,%1,%2,%3}, {%4,%5,%6,%7}, {%8,%9}, {%0,%1,%2,%3};"
        : "+f"(c[0]), "+f"(c[1]), "+f"(c[2]), "+f"(c[3])
        : "r"(a0), "r"(a1), "r"(a2), "r"(a3), "r"(b0), "r"(b1));
}

// ======================= T1: tensor-core transform =========================
// CTA: 128 m-rows x 96 cols, K=64. 256 thr = 8 warps; warp tile 32m x 48n.
__global__ void __launch_bounds__(256)
t1_mma_kernel(const float* __restrict__ X, const float* __restrict__ W,
              __half2* __restrict__ Y, int n_nodes)
{
    constexpr int XSTR = 72;    // halves/row (144B: 4-bank shift, ldmatrix clean)
    constexpr int WSTR = 104;   // halves/row (208B: 20-bank shift, ldmatrix clean)
    __shared__ __half Xh[128 * XSTR];   // 18432 B
    __shared__ __half Wh[64 * WSTR];    // 13312 B

    const int tid = threadIdx.x;
    const int mt0 = blockIdx.x * 128;

    // Stage W1 -> Wh[f][k*32+h] fp16
    for (int i = tid; i < 64 * 96; i += 256) {
        const int f = i / 96, j = i % 96;
        Wh[f * WSTR + j] = __float2half(W[((size_t)(j >> 5) * 64 + f) * 32 + (j & 31)]);
    }
    // Stage X -> Xh[m][f] fp16 (zero-fill tail rows)
    for (int i = tid; i < 128 * 32; i += 256) {
        const int m = i >> 5, f2 = i & 31;
        float2 v = make_float2(0.f, 0.f);
        if (mt0 + m < n_nodes)
            v = *(const float2*)(X + (size_t)(mt0 + m) * 64 + 2 * f2);
        *(__half2*)&Xh[m * XSTR + 2 * f2] = __floats2half2_rn(v.x, v.y);
    }
    __syncthreads();

    const int lane = tid & 31;
    const int wid  = tid >> 5;
    const int wm = wid >> 1;            // 0..3: rows 32*wm
    const int wn = wid & 1;             // 0..1: cols 48*wn
    const int g = lane >> 2, t = lane & 3;

    float acc[2][6][4];
    #pragma unroll
    for (int mi = 0; mi < 2; mi++)
        #pragma unroll
        for (int ni = 0; ni < 6; ni++)
            #pragma unroll
            for (int c = 0; c < 4; c++) acc[mi][ni][c] = 0.f;

    const uint32_t xbase = (uint32_t)__cvta_generic_to_shared(Xh);
    const uint32_t wbase = (uint32_t)__cvta_generic_to_shared(Wh);
    const int arow  = wm * 32 + (lane & 15);
    const int acol8 = 8 * (lane >> 4);
    const int brow  = lane & 15;

    #pragma unroll
    for (int kt = 0; kt < 4; kt++) {
        const int k0 = kt * 16;
        uint32_t a[2][4];
        #pragma unroll
        for (int mi = 0; mi < 2; mi++) {
            const uint32_t addr = xbase + ((arow + mi * 16) * XSTR + k0 + acol8) * 2;
            ldsm_x4(a[mi][0], a[mi][1], a[mi][2], a[mi][3], addr);
        }
        #pragma unroll
        for (int ni = 0; ni < 6; ni++) {
            uint32_t b0, b1;
            const uint32_t addr = wbase + ((k0 + brow) * WSTR + wn * 48 + ni * 8) * 2;
            ldsm_x2_t(b0, b1, addr);
            #pragma unroll
            for (int mi = 0; mi < 2; mi++)
                mma16816(acc[mi][ni], a[mi][0], a[mi][1], a[mi][2], a[mi][3], b0, b1);
        }
    }

    // Epilogue: c0/c1 -> (row g), c2/c3 -> (row g+8); half2 col index n/2.
    #pragma unroll
    for (int mi = 0; mi < 2; mi++) {
        const int r0 = mt0 + wm * 32 + mi * 16 + g;
        #pragma unroll
        for (int ni = 0; ni < 6; ni++) {
            const int cidx = (wn * 48 + ni * 8) / 2 + t;
            if (r0 < n_nodes)
                Y[(size_t)r0 * 48 + cidx] = __floats2half2_rn(acc[mi][ni][0], acc[mi][ni][1]);
            if (r0 + 8 < n_nodes)
                Y[(size_t)(r0 + 8) * 48 + cidx] = __floats2half2_rn(acc[mi][ni][2], acc[mi][ni][3]);
        }
    }
}

// ============================== gaussians ==================================
#define LOAD_GAUSS_PARAMS()                                                   \
    const float m0_ = mu[0], m1_ = mu[1], m2_ = mu[2],                        \
                m3_ = mu[3], m4_ = mu[4], m5_ = mu[5];                        \
    float s_;                                                                 \
    s_ = sigma[0]; const float i0_ = 1.f/(s_*s_);                             \
    s_ = sigma[1]; const float i1_ = 1.f/(s_*s_);                             \
    s_ = sigma[2]; const float i2_ = 1.f/(s_*s_);                             \
    s_ = sigma[3]; const float i3_ = 1.f/(s_*s_);                             \
    s_ = sigma[4]; const float i4_ = 1.f/(s_*s_);                             \
    s_ = sigma[5]; const float i5_ = 1.f/(s_*s_);

#define GAUSS3(pv, g0, g1, g2) do {                                           \
    float dx_, dy_, q_;                                                       \
    dx_ = (pv).x - m0_; dy_ = (pv).y - m1_;                                   \
    q_ = dx_*dx_*i0_ + dy_*dy_*i1_; g0 = __expf(-0.5f * q_);                  \
    dx_ = (pv).x - m2_; dy_ = (pv).y - m3_;                                   \
    q_ = dx_*dx_*i2_ + dy_*dy_*i3_; g1 = __expf(-0.5f * q_);                  \
    dx_ = (pv).x - m4_; dy_ = (pv).y - m5_;                                   \
    q_ = dx_*dx_*i4_ + dy_*dy_*i5_; g2 = __expf(-0.5f * q_);                  \
} while (0)

// ============== G1 + T2 fused: gather -> h (smem) -> y2 = h*W2 =============
template<int NWARP, int GRP>
__global__ void __launch_bounds__(NWARP * 32)
g1t2_kernel(const int* __restrict__ row_ptr, const int* __restrict__ col_idx,
            const float2* __restrict__ p,
            const float* __restrict__ mu, const float* __restrict__ sigma,
            const uint2* __restrict__ y,      // y1: [N][24] uint2
            const float* __restrict__ W2,     // [3][32][16]
            unsigned* __restrict__ y2,        // [N][32] uint (128B rows)
            int n_nodes)
{
    constexpr int CAP = GRP * 16;
    __shared__ float4 stg[NWARP][CAP];
    __shared__ float  hbuf[NWARP][GRP][32];
    __shared__ ull    wp[24 * 33];            // W2 pairs, stride 33

    const int tid  = threadIdx.x;
    const int lane = tid & 31;
    const int wid  = tid >> 5;

    for (int i = tid; i < 24 * 32; i += NWARP * 32) {
        const int l = i / 32, f = i % 32;
        const int hp = l / 3, k = l % 3;
        const float* wrow = W2 + ((size_t)k * 32 + f) * 16 + 2 * hp;
        wp[l * 33 + f] = pk2(wrow[0], wrow[1]);
    }
    __syncthreads();

    const int base = (blockIdx.x * NWARP + wid) * GRP;
    if (base >= n_nodes) return;

    LOAD_GAUSS_PARAMS();

    const int ng   = min(GRP, n_nodes - base);
    const int e0   = row_ptr[base];
    const int ecnt = row_ptr[base + ng] - e0;
    const bool fast = (ecnt <= CAP);

    if (fast) {
        for (int j = lane; j < ecnt; j += 32) {
            const int e = e0 + j;
            const int c = col_idx[e];
            const float2 pv = __ldg(p + e);
            float g0, g1, g2; GAUSS3(pv, g0, g1, g2);
            stg[wid][j] = make_float4(g0, g1, g2, __int_as_float(c));
        }
    }
    __syncwarp();

    const int s  = lane >> 3;
    const int hl = lane & 7;

    #pragma unroll
    for (int pi = 0; pi < GRP / 4; pi++) {
        const int n = base + pi * 4 + s;
        const bool valid = (n < n_nodes);
        const int nc  = valid ? n : base;
        const int st  = __ldg(row_ptr + nc);
        const int deg = valid ? (__ldg(row_ptr + nc + 1) - st) : 0;

        ull a[3][2];
        #pragma unroll
        for (int k = 0; k < 3; k++) { a[k][0] = 0ull; a[k][1] = 0ull; }

        if (fast) {
            const float4* sd = &stg[wid][st - e0];
            const bool u16 = __all_sync(0xffffffffu, deg == 16);
            #define G1_BODY(J) do {                                           \
                const float4 ed = sd[(J)];                                    \
                const int c = __float_as_int(ed.w);                           \
                const uint2* yr = y + (size_t)c * 24 + hl;                    \
                const uint2 v0 = __ldg(yr);                                   \
                const uint2 v1 = __ldg(yr + 8);                               \
                const uint2 v2 = __ldg(yr + 16);                              \
                const float2 c00 = __half22float2(*(const __half2*)&v0.x);    \
                const float2 c01 = __half22float2(*(const __half2*)&v0.y);    \
                const float2 c10 = __half22float2(*(const __half2*)&v1.x);    \
                const float2 c11 = __half22float2(*(const __half2*)&v1.y);    \
                const float2 c20 = __half22float2(*(const __half2*)&v2.x);    \
                const float2 c21 = __half22float2(*(const __half2*)&v2.y);    \
                const ull w0 = pk2(ed.x, ed.x);                               \
                const ull w1 = pk2(ed.y, ed.y);                               \
                const ull w2 = pk2(ed.z, ed.z);                               \
                ffma2(a[0][0], w0, pk2(c00.x, c00.y));                        \
                ffma2(a[0][1], w0, pk2(c01.x, c01.y));                        \
                ffma2(a[1][0], w1, pk2(c10.x, c10.y));                        \
                ffma2(a[1][1], w1, pk2(c11.x, c11.y));                        \
                ffma2(a[2][0], w2, pk2(c20.x, c20.y));                        \
                ffma2(a[2][1], w2, pk2(c21.x, c21.y));                        \
            } while (0)
            if (u16) {
                #pragma unroll
                for (int j = 0; j < 16; j++) G1_BODY(j);
            } else {
                const int maxd = __reduce_max_sync(0xffffffffu, deg);
                for (int j = 0; j < maxd; j++)
                    if (j < deg) G1_BODY(j);
            }
            #undef G1_BODY
        } else {
            const int maxd = __reduce_max_sync(0xffffffffu, deg);
            for (int j = 0; j < maxd; j++) {
                if (j < deg) {
                    const int e = st + j;
                    const int c = __ldg(col_idx + e);
                    const float2 pv = __ldg(p + e);
                    float g0, g1, g2; GAUSS3(pv, g0, g1, g2);
                    const uint2* yr = y + (size_t)c * 24 + hl;
                    const uint2 v0 = __ldg(yr);
                    const uint2 v1 = __ldg(yr + 8);
                    const uint2 v2 = __ldg(yr + 16);
                    const float2 c00 = __half22float2(*(const __half2*)&v0.x);
                    const float2 c01 = __half22float2(*(const __half2*)&v0.y);
                    const float2 c10 = __half22float2(*(const __half2*)&v1.x);
                    const float2 c11 = __half22float2(*(const __half2*)&v1.y);
                    const float2 c20 = __half22float2(*(const __half2*)&v2.x);
                    const float2 c21 = __half22float2(*(const __half2*)&v2.y);
                    ffma2(a[0][0], pk2(g0, g0), pk2(c00.x, c00.y));
                    ffma2(a[0][1], pk2(g0, g0), pk2(c01.x, c01.y));
                    ffma2(a[1][0], pk2(g1, g1), pk2(c10.x, c10.y));
                    ffma2(a[1][1], pk2(g1, g1), pk2(c11.x, c11.y));
                    ffma2(a[2][0], pk2(g2, g2), pk2(c20.x, c20.y));
                    ffma2(a[2][1], pk2(g2, g2), pk2(c21.x, c21.y));
                }
            }
        }

        float p00, p01, p10, p11, q00, q01, q10, q11, r00, r01, r10, r11;
        upk2(a[0][0], p00, p01); upk2(a[0][1], p10, p11);
        upk2(a[1][0], q00, q01); upk2(a[1][1], q10, q11);
        upk2(a[2][0], r00, r01); upk2(a[2][1], r10, r11);
        float4 o;
        o.x = p00 + q00 + r00;
        o.y = p01 + q01 + r01;
        o.z = p10 + q10 + r10;
        o.w = p11 + q11 + r11;
        *(float4*)&hbuf[wid][pi * 4 + s][4 * hl] = o;
    }
    __syncwarp();

    // fused T2: y2[g] = h[g] * W2
    const int wl = (lane < 24) ? lane : 0;
    const ull* wcol = wp + wl * 33;

    ull acc[GRP];
    #pragma unroll
    for (int g = 0; g < GRP; g++) acc[g] = 0ull;

    #pragma unroll
    for (int fc = 0; fc < 8; fc++) {
        ull wr[4];
        #pragma unroll
        for (int f4 = 0; f4 < 4; f4++) wr[f4] = wcol[fc * 4 + f4];
        #pragma unroll
        for (int g = 0; g < GRP; g++) {
            const float4 hv = *(const float4*)&hbuf[wid][g][fc * 4];
            ffma2(acc[g], pk2(hv.x, hv.x), wr[0]);
            ffma2(acc[g], pk2(hv.y, hv.y), wr[1]);
            ffma2(acc[g], pk2(hv.z, hv.z), wr[2]);
            ffma2(acc[g], pk2(hv.w, hv.w), wr[3]);
        }
    }

    const int oidx = (lane / 3) * 4 + (lane % 3);
    #pragma unroll
    for (int g = 0; g < GRP; g++) {
        const int n = base + g;
        if (lane < 24 && n < n_nodes) {
            float lo, hi; upk2(acc[g], lo, hi);
            const __half2 hv = __floats2half2_rn(lo, hi);
            y2[(size_t)n * 32 + oidx] = *(const unsigned*)&hv;
        }
    }
}

// ---- G2: H=16, padded 128B rows; 8 lanes/node, 1x LDG.128 per edge --------
template<int NWARP, int GRP>
__global__ void __launch_bounds__(NWARP * 32)
gather_h16(const int* __restrict__ row_ptr, const int* __restrict__ col_idx,
           const float2* __restrict__ p,
           const float* __restrict__ mu, const float* __restrict__ sigma,
           const uint4* __restrict__ y,     // [N][8] 16B chunks
           float* __restrict__ out,         // [N][16] f32
           int n_nodes)
{
    constexpr int CAP = GRP * 16;
    __shared__ float4 stg[NWARP][CAP];

    const int lane = threadIdx.x & 31;
    const int wid  = threadIdx.x >> 5;
    const int s    = lane >> 3;
    const int hl   = lane & 7;
    const int base = (blockIdx.x * NWARP + wid) * GRP;
    if (base >= n_nodes) return;

    LOAD_GAUSS_PARAMS();

    const int ng   = min(GRP, n_nodes - base);
    const int e0   = row_ptr[base];
    const int ecnt = row_ptr[base + ng] - e0;
    const bool fast = (ecnt <= CAP);

    if (fast) {
        for (int j = lane; j < ecnt; j += 32) {
            const int e = e0 + j;
            const int c = col_idx[e];
            const float2 pv = __ldg(p + e);
            float g0, g1, g2; GAUSS3(pv, g0, g1, g2);
            stg[wid][j] = make_float4(g0, g1, g2, __int_as_float(c));
        }
    }
    __syncwarp();

    #pragma unroll
    for (int pi = 0; pi < GRP / 4; pi++) {
        const int n = base + pi * 4 + s;
        const bool valid = (n < n_nodes);
        const int nc  = valid ? n : base;
        const int st  = __ldg(row_ptr + nc);
        const int deg = valid ? (__ldg(row_ptr + nc + 1) - st) : 0;

        ull a0 = 0ull, a1 = 0ull, a2 = 0ull;

        if (fast) {
            const float4* sd = &stg[wid][st - e0];
            const bool u16 = __all_sync(0xffffffffu, deg == 16);
            #define G2_BODY(J) do {                                           \
                const float4 ed = sd[(J)];                                    \
                const int c = __float_as_int(ed.w);                           \
                const uint4 v = __ldg(y + (size_t)c * 8 + hl);                \
                const float2 f0 = __half22float2(*(const __half2*)&v.x);      \
                const float2 f1 = __half22float2(*(const __half2*)&v.y);      \
                const float2 f2 = __half22float2(*(const __half2*)&v.z);      \
                ffma2(a0, pk2(ed.x, ed.x), pk2(f0.x, f0.y));                  \
                ffma2(a1, pk2(ed.y, ed.y), pk2(f1.x, f1.y));                  \
                ffma2(a2, pk2(ed.z, ed.z), pk2(f2.x, f2.y));                  \
            } while (0)
            if (u16) {
                #pragma unroll
                for (int j = 0; j < 16; j++) G2_BODY(j);
            } else {
                const int maxd = __reduce_max_sync(0xffffffffu, deg);
                for (int j = 0; j < maxd; j++)
                    if (j < deg) G2_BODY(j);
            }
            #undef G2_BODY
        } else {
            const int maxd = __reduce_max_sync(0xffffffffu, deg);
            for (int j = 0; j < maxd; j++) {
                if (j < deg) {
                    const int e = st + j;
                    const int c = __ldg(col_idx + e);
                    const float2 pv = __ldg(p + e);
                    float g0, g1, g2; GAUSS3(pv, g0, g1, g2);
                    const uint4 v = __ldg(y + (size_t)c * 8 + hl);
                    const float2 f0 = __half22float2(*(const __half2*)&v.x);
                    const float2 f1 = __half22float2(*(const __half2*)&v.y);
                    const float2 f2 = __half22float2(*(const __half2*)&v.z);
                    ffma2(a0, pk2(g0, g0), pk2(f0.x, f0.y));
                    ffma2(a1, pk2(g1, g1), pk2(f1.x, f1.y));
                    ffma2(a2, pk2(g2, g2), pk2(f2.x, f2.y));
                }
            }
        }

        if (valid) {
            float x0, x1, y0v, y1v, z0, z1;
            upk2(a0, x0, x1); upk2(a1, y0v, y1v); upk2(a2, z0, z1);
            float2 o = make_float2(x0 + y0v + z0, x1 + y1v + z1);
            *(float2*)(out + (size_t)n * 16 + 2 * hl) = o;
        }
    }
}

// =============================== launch ====================================
extern "C" void kernel_launch(void* const* d_in, const int* in_sizes, int n_in,
                              void* d_out, int out_size)
{
    const int*    row_ptr = (const int*)d_in[0];    // int32 (JAX x64 disabled)
    const int*    col_idx = (const int*)d_in[1];
    const float*  x       = (const float*)d_in[2];
    const float2* p       = (const float2*)d_in[3];
    const float*  mu      = (const float*)d_in[4];
    const float*  sg      = (const float*)d_in[5];
    const float*  W1      = (const float*)d_in[6];
    const float*  W2      = (const float*)d_in[7];

    const int n_nodes = in_sizes[0] - 1;

    void *y1p, *y2p;
    cudaGetSymbolAddress(&y1p, g_y1);
    cudaGetSymbolAddress(&y2p, g_y2);

    constexpr int NWARP = 8;
    constexpr int GRP   = 8;
    const int gblocks = (n_nodes + NWARP * GRP - 1) / (NWARP * GRP);
    const int tblocks = (n_nodes + 127) / 128;

    // T1: y1 = x * W1  (tensor cores; fp16 unpadded rows)
    t1_mma_kernel<<<tblocks, 256>>>(x, W1, (__half2*)y1p, n_nodes);
    // G1+T2: h = gather(y1) in smem; y2 = h*W2 (padded 128B rows)
    g1t2_kernel<NWARP, GRP><<<gblocks, NWARP * 32>>>(
        row_ptr, col_idx, p, mu, sg, (const uint2*)y1p, W2,
        (unsigned*)y2p, n_nodes);
    // G2: out = gather(y2)  (8 lanes/node, 1x LDG.128/edge)
    gather_h16<NWARP, GRP><<<gblocks, NWARP * 32>>>(
        row_ptr, col_idx, p, mu, sg, (const uint4*)y2p, (float*)d_out, n_nodes);
}

// round 12
// speedup vs baseline: 1.2909x; 1.1072x over previous
#include <cuda_runtime.h>
#include <cuda_fp16.h>
#include <cstddef>
#include <cstdint>

// ---------------------------------------------------------------------------
// GMM (MoNet) graph conv — 3-kernel pipeline:
//   T1:   y1 = x*W1 via mma.sync.m16n8k16 (fp16 in, f32 acc, fp16 out),
//         MT=64 tiles, smem-transposed coalesced epilogue
//   G1T2: h[n] = gather(y1) (smem only), then per-node GEMM y2 = h*W2,
//         y2 stored as padded 128B rows [8 chunks][{k0,k1,k2,pad} half2]
//   G2:   out[n] = gather(y2), 1 LDG.128 per edge-lane (1 line/node)
// ---------------------------------------------------------------------------

#define MAXN 131072
__device__ __half g_y1[MAXN * 96];   // [N][3][32]  unpadded, 192B rows
__device__ __half g_y2[MAXN * 64];   // [N][8 chunks][8 halves], 128B rows

typedef unsigned long long ull;

__device__ __forceinline__ ull pk2(float x, float y) {
    ull r; asm("mov.b64 %0, {%1,%2};" : "=l"(r) : "f"(x), "f"(y)); return r;
}
__device__ __forceinline__ void upk2(ull v, float& x, float& y) {
    asm("mov.b64 {%0,%1}, %2;" : "=f"(x), "=f"(y) : "l"(v));
}
__device__ __forceinline__ void ffma2(ull& d, ull a, ull b) {
    asm("fma.rn.f32x2 %0, %1, %2, %0;" : "+l"(d) : "l"(a), "l"(b));
}

__device__ __forceinline__ void ldsm_x4(uint32_t& r0, uint32_t& r1,
                                        uint32_t& r2, uint32_t& r3, uint32_t a) {
    asm volatile("ldmatrix.sync.aligned.m8n8.x4.shared.b16 {%0,%1,%2,%3}, [%4];"
                 : "=r"(r0), "=r"(r1), "=r"(r2), "=r"(r3) : "r"(a));
}
__device__ __forceinline__ void ldsm_x2_t(uint32_t& r0, uint32_t& r1, uint32_t a) {
    asm volatile("ldmatrix.sync.aligned.m8n8.x2.trans.shared.b16 {%0,%1}, [%2];"
                 : "=r"(r0), "=r"(r1) : "r"(a));
}
__device__ __forceinline__ void mma16816(float* c,
    uint32_t a0, uint32_t a1, uint32_t a2, uint32_t a3, uint32_t b0, uint32_t b1) {
    asm volatile(
        "mma.sync.aligned.m16n8k16.row.col.f32.f16.f16.f32 "
        "{%0,%1,%2,%3}, {%4,%5,%6,%7}, {%8,%9}, {%0,%1,%2,%3};"
        : "+f"(c[0]), "+f"(c[1]), "+f"(c[2]), "+f"(c[3])
        : "r"(a0), "r"(a1), "r"(a2), "r"(a3), "r"(b0), "r"(b1));
}

// ======================= T1: tensor-core transform =========================
// CTA: 64 m-rows x 96 cols, K=64. 256 thr = 8 warps; warp tile 16m x 48n.
__global__ void __launch_bounds__(256)
t1_mma_kernel(const float* __restrict__ X, const float* __restrict__ W,
              uint4* __restrict__ Yg, int n_nodes)
{
    constexpr int MT   = 64;
    constexpr int XSTR = 72;    // halves/row (144B rows, 16B aligned)
    constexpr int WSTR = 104;   // halves/row (208B rows)
    constexpr int SSTR = 52;    // half2/row  (208B rows; g*20 mod 32 distinct)

    __shared__ __half  Xh[MT * XSTR];    //  9216 B
    __shared__ __half  Wh[64 * WSTR];    // 13312 B
    __shared__ __half2 Ys[MT * SSTR];    // 13312 B

    const int tid = threadIdx.x;
    const int mt0 = blockIdx.x * MT;

    // Stage W1 -> Wh[f][k*32+h] fp16 (coalesced over j)
    for (int i = tid; i < 64 * 96; i += 256) {
        const int f = i / 96, j = i % 96;
        Wh[f * WSTR + j] = __float2half(W[((size_t)(j >> 5) * 64 + f) * 32 + (j & 31)]);
    }
    // Stage X -> Xh[m][f] fp16 via float4 loads (4 per thread, independent)
    #pragma unroll
    for (int k = 0; k < 4; k++) {
        const int i = tid + k * 256;               // < 1024
        const int m = i >> 4, f4 = i & 15;
        float4 v = make_float4(0.f, 0.f, 0.f, 0.f);
        if (mt0 + m < n_nodes)
            v = *(const float4*)(X + (size_t)(mt0 + m) * 64 + 4 * f4);
        uint2 hv;
        __half2 h0 = __floats2half2_rn(v.x, v.y);
        __half2 h1 = __floats2half2_rn(v.z, v.w);
        hv.x = *(const uint32_t*)&h0;
        hv.y = *(const uint32_t*)&h1;
        *(uint2*)&Xh[m * XSTR + 4 * f4] = hv;
    }
    __syncthreads();

    const int lane = tid & 31;
    const int wid  = tid >> 5;
    const int wm = wid >> 1;            // 0..3: rows 16*wm
    const int wn = wid & 1;             // 0..1: cols 48*wn
    const int g = lane >> 2, t = lane & 3;

    float acc[6][4];
    #pragma unroll
    for (int ni = 0; ni < 6; ni++)
        #pragma unroll
        for (int c = 0; c < 4; c++) acc[ni][c] = 0.f;

    const uint32_t xbase = (uint32_t)__cvta_generic_to_shared(Xh);
    const uint32_t wbase = (uint32_t)__cvta_generic_to_shared(Wh);
    const int arow  = wm * 16 + (lane & 15);
    const int acol8 = 8 * (lane >> 4);
    const int brow  = lane & 15;

    #pragma unroll
    for (int kt = 0; kt < 4; kt++) {
        const int k0 = kt * 16;
        uint32_t a0, a1, a2, a3;
        ldsm_x4(a0, a1, a2, a3, xbase + (arow * XSTR + k0 + acol8) * 2);
        #pragma unroll
        for (int ni = 0; ni < 6; ni++) {
            uint32_t b0, b1;
            ldsm_x2_t(b0, b1, wbase + ((k0 + brow) * WSTR + wn * 48 + ni * 8) * 2);
            mma16816(acc[ni], a0, a1, a2, a3, b0, b1);
        }
    }

    // Epilogue: accs -> Ys (conflict-free), then coalesced uint4 copy to gmem.
    #pragma unroll
    for (int ni = 0; ni < 6; ni++) {
        const int cidx = wn * 24 + ni * 4 + t;
        Ys[(wm * 16 + g)     * SSTR + cidx] = __floats2half2_rn(acc[ni][0], acc[ni][1]);
        Ys[(wm * 16 + g + 8) * SSTR + cidx] = __floats2half2_rn(acc[ni][2], acc[ni][3]);
    }
    __syncthreads();

    const uint4* Ysv = (const uint4*)Ys;     // 13 uint4 per row (208B)
    #pragma unroll
    for (int k = 0; k < 3; k++) {
        const int i = tid + k * 256;         // < 768 = 64*12
        const int r = i / 12, c = i % 12;
        if (mt0 + r < n_nodes)
            Yg[(size_t)(mt0 + r) * 12 + c] = Ysv[r * 13 + c];
    }
}

// ============================== gaussians ==================================
#define LOAD_GAUSS_PARAMS()                                                   \
    const float m0_ = mu[0], m1_ = mu[1], m2_ = mu[2],                        \
                m3_ = mu[3], m4_ = mu[4], m5_ = mu[5];                        \
    float s_;                                                                 \
    s_ = sigma[0]; const float i0_ = 1.f/(s_*s_);                             \
    s_ = sigma[1]; const float i1_ = 1.f/(s_*s_);                             \
    s_ = sigma[2]; const float i2_ = 1.f/(s_*s_);                             \
    s_ = sigma[3]; const float i3_ = 1.f/(s_*s_);                             \
    s_ = sigma[4]; const float i4_ = 1.f/(s_*s_);                             \
    s_ = sigma[5]; const float i5_ = 1.f/(s_*s_);

#define GAUSS3(pv, g0, g1, g2) do {                                           \
    float dx_, dy_, q_;                                                       \
    dx_ = (pv).x - m0_; dy_ = (pv).y - m1_;                                   \
    q_ = dx_*dx_*i0_ + dy_*dy_*i1_; g0 = __expf(-0.5f * q_);                  \
    dx_ = (pv).x - m2_; dy_ = (pv).y - m3_;                                   \
    q_ = dx_*dx_*i2_ + dy_*dy_*i3_; g1 = __expf(-0.5f * q_);                  \
    dx_ = (pv).x - m4_; dy_ = (pv).y - m5_;                                   \
    q_ = dx_*dx_*i4_ + dy_*dy_*i5_; g2 = __expf(-0.5f * q_);                  \
} while (0)

// ============== G1 + T2 fused: gather -> h (smem) -> y2 = h*W2 =============
template<int NWARP, int GRP>
__global__ void __launch_bounds__(NWARP * 32)
g1t2_kernel(const int* __restrict__ row_ptr, const int* __restrict__ col_idx,
            const float2* __restrict__ p,
            const float* __restrict__ mu, const float* __restrict__ sigma,
            const uint2* __restrict__ y,      // y1: [N][24] uint2
            const float* __restrict__ W2,     // [3][32][16]
            unsigned* __restrict__ y2,        // [N][32] uint (128B rows)
            int n_nodes)
{
    constexpr int CAP = GRP * 16;
    __shared__ float4 stg[NWARP][CAP];
    __shared__ float  hbuf[NWARP][GRP][32];
    __shared__ ull    wp[24 * 33];            // W2 pairs, stride 33

    const int tid  = threadIdx.x;
    const int lane = tid & 31;
    const int wid  = tid >> 5;

    for (int i = tid; i < 24 * 32; i += NWARP * 32) {
        const int l = i / 32, f = i % 32;
        const int hp = l / 3, k = l % 3;
        const float* wrow = W2 + ((size_t)k * 32 + f) * 16 + 2 * hp;
        wp[l * 33 + f] = pk2(wrow[0], wrow[1]);
    }
    __syncthreads();

    const int base = (blockIdx.x * NWARP + wid) * GRP;
    if (base >= n_nodes) return;

    LOAD_GAUSS_PARAMS();

    const int ng   = min(GRP, n_nodes - base);
    const int e0   = row_ptr[base];
    const int ecnt = row_ptr[base + ng] - e0;
    const bool fast = (ecnt <= CAP);

    if (fast) {
        for (int j = lane; j < ecnt; j += 32) {
            const int e = e0 + j;
            const int c = col_idx[e];
            const float2 pv = __ldg(p + e);
            float g0, g1, g2; GAUSS3(pv, g0, g1, g2);
            stg[wid][j] = make_float4(g0, g1, g2, __int_as_float(c));
        }
    }
    __syncwarp();

    const int s  = lane >> 3;
    const int hl = lane & 7;

    #pragma unroll
    for (int pi = 0; pi < GRP / 4; pi++) {
        const int n = base + pi * 4 + s;
        const bool valid = (n < n_nodes);
        const int nc  = valid ? n : base;
        const int st  = __ldg(row_ptr + nc);
        const int deg = valid ? (__ldg(row_ptr + nc + 1) - st) : 0;

        ull a[3][2];
        #pragma unroll
        for (int k = 0; k < 3; k++) { a[k][0] = 0ull; a[k][1] = 0ull; }

        if (fast) {
            const float4* sd = &stg[wid][st - e0];
            const bool u16 = __all_sync(0xffffffffu, deg == 16);
            #define G1_BODY(J) do {                                           \
                const float4 ed = sd[(J)];                                    \
                const int c = __float_as_int(ed.w);                           \
                const uint2* yr = y + (size_t)c * 24 + hl;                    \
                const uint2 v0 = __ldg(yr);                                   \
                const uint2 v1 = __ldg(yr + 8);                               \
                const uint2 v2 = __ldg(yr + 16);                              \
                const float2 c00 = __half22float2(*(const __half2*)&v0.x);    \
                const float2 c01 = __half22float2(*(const __half2*)&v0.y);    \
                const float2 c10 = __half22float2(*(const __half2*)&v1.x);    \
                const float2 c11 = __half22float2(*(const __half2*)&v1.y);    \
                const float2 c20 = __half22float2(*(const __half2*)&v2.x);    \
                const float2 c21 = __half22float2(*(const __half2*)&v2.y);    \
                const ull w0 = pk2(ed.x, ed.x);                               \
                const ull w1 = pk2(ed.y, ed.y);                               \
                const ull w2 = pk2(ed.z, ed.z);                               \
                ffma2(a[0][0], w0, pk2(c00.x, c00.y));                        \
                ffma2(a[0][1], w0, pk2(c01.x, c01.y));                        \
                ffma2(a[1][0], w1, pk2(c10.x, c10.y));                        \
                ffma2(a[1][1], w1, pk2(c11.x, c11.y));                        \
                ffma2(a[2][0], w2, pk2(c20.x, c20.y));                        \
                ffma2(a[2][1], w2, pk2(c21.x, c21.y));                        \
            } while (0)
            if (u16) {
                #pragma unroll
                for (int j = 0; j < 16; j++) G1_BODY(j);
            } else {
                const int maxd = __reduce_max_sync(0xffffffffu, deg);
                for (int j = 0; j < maxd; j++)
                    if (j < deg) G1_BODY(j);
            }
            #undef G1_BODY
        } else {
            const int maxd = __reduce_max_sync(0xffffffffu, deg);
            for (int j = 0; j < maxd; j++) {
                if (j < deg) {
                    const int e = st + j;
                    const int c = __ldg(col_idx + e);
                    const float2 pv = __ldg(p + e);
                    float g0, g1, g2; GAUSS3(pv, g0, g1, g2);
                    const uint2* yr = y + (size_t)c * 24 + hl;
                    const uint2 v0 = __ldg(yr);
                    const uint2 v1 = __ldg(yr + 8);
                    const uint2 v2 = __ldg(yr + 16);
                    const float2 c00 = __half22float2(*(const __half2*)&v0.x);
                    const float2 c01 = __half22float2(*(const __half2*)&v0.y);
                    const float2 c10 = __half22float2(*(const __half2*)&v1.x);
                    const float2 c11 = __half22float2(*(const __half2*)&v1.y);
                    const float2 c20 = __half22float2(*(const __half2*)&v2.x);
                    const float2 c21 = __half22float2(*(const __half2*)&v2.y);
                    ffma2(a[0][0], pk2(g0, g0), pk2(c00.x, c00.y));
                    ffma2(a[0][1], pk2(g0, g0), pk2(c01.x, c01.y));
                    ffma2(a[1][0], pk2(g1, g1), pk2(c10.x, c10.y));
                    ffma2(a[1][1], pk2(g1, g1), pk2(c11.x, c11.y));
                    ffma2(a[2][0], pk2(g2, g2), pk2(c20.x, c20.y));
                    ffma2(a[2][1], pk2(g2, g2), pk2(c21.x, c21.y));
                }
            }
        }

        float p00, p01, p10, p11, q00, q01, q10, q11, r00, r01, r10, r11;
        upk2(a[0][0], p00, p01); upk2(a[0][1], p10, p11);
        upk2(a[1][0], q00, q01); upk2(a[1][1], q10, q11);
        upk2(a[2][0], r00, r01); upk2(a[2][1], r10, r11);
        float4 o;
        o.x = p00 + q00 + r00;
        o.y = p01 + q01 + r01;
        o.z = p10 + q10 + r10;
        o.w = p11 + q11 + r11;
        *(float4*)&hbuf[wid][pi * 4 + s][4 * hl] = o;
    }
    __syncwarp();

    // fused T2: y2[g] = h[g] * W2
    const int wl = (lane < 24) ? lane : 0;
    const ull* wcol = wp + wl * 33;

    ull acc[GRP];
    #pragma unroll
    for (int g = 0; g < GRP; g++) acc[g] = 0ull;

    #pragma unroll
    for (int fc = 0; fc < 8; fc++) {
        ull wr[4];
        #pragma unroll
        for (int f4 = 0; f4 < 4; f4++) wr[f4] = wcol[fc * 4 + f4];
        #pragma unroll
        for (int g = 0; g < GRP; g++) {
            const float4 hv = *(const float4*)&hbuf[wid][g][fc * 4];
            ffma2(acc[g], pk2(hv.x, hv.x), wr[0]);
            ffma2(acc[g], pk2(hv.y, hv.y), wr[1]);
            ffma2(acc[g], pk2(hv.z, hv.z), wr[2]);
            ffma2(acc[g], pk2(hv.w, hv.w), wr[3]);
        }
    }

    const int oidx = (lane / 3) * 4 + (lane % 3);
    #pragma unroll
    for (int g = 0; g < GRP; g++) {
        const int n = base + g;
        if (lane < 24 && n < n_nodes) {
            float lo, hi; upk2(acc[g], lo, hi);
            const __half2 hv = __floats2half2_rn(lo, hi);
            y2[(size_t)n * 32 + oidx] = *(const unsigned*)&hv;
        }
    }
}

// ---- G2: H=16, padded 128B rows; 8 lanes/node, 1x LDG.128 per edge --------
template<int NWARP, int GRP>
__global__ void __launch_bounds__(NWARP * 32)
gather_h16(const int* __restrict__ row_ptr, const int* __restrict__ col_idx,
           const float2* __restrict__ p,
           const float* __restrict__ mu, const float* __restrict__ sigma,
           const uint4* __restrict__ y,     // [N][8] 16B chunks
           float* __restrict__ out,         // [N][16] f32
           int n_nodes)
{
    constexpr int CAP = GRP * 16;
    __shared__ float4 stg[NWARP][CAP];

    const int lane = threadIdx.x & 31;
    const int wid  = threadIdx.x >> 5;
    const int s    = lane >> 3;
    const int hl   = lane & 7;
    const int base = (blockIdx.x * NWARP + wid) * GRP;
    if (base >= n_nodes) return;

    LOAD_GAUSS_PARAMS();

    const int ng   = min(GRP, n_nodes - base);
    const int e0   = row_ptr[base];
    const int ecnt = row_ptr[base + ng] - e0;
    const bool fast = (ecnt <= CAP);

    if (fast) {
        for (int j = lane; j < ecnt; j += 32) {
            const int e = e0 + j;
            const int c = col_idx[e];
            const float2 pv = __ldg(p + e);
            float g0, g1, g2; GAUSS3(pv, g0, g1, g2);
            stg[wid][j] = make_float4(g0, g1, g2, __int_as_float(c));
        }
    }
    __syncwarp();

    #pragma unroll
    for (int pi = 0; pi < GRP / 4; pi++) {
        const int n = base + pi * 4 + s;
        const bool valid = (n < n_nodes);
        const int nc  = valid ? n : base;
        const int st  = __ldg(row_ptr + nc);
        const int deg = valid ? (__ldg(row_ptr + nc + 1) - st) : 0;

        ull a0 = 0ull, a1 = 0ull, a2 = 0ull;

        if (fast) {
            const float4* sd = &stg[wid][st - e0];
            const bool u16 = __all_sync(0xffffffffu, deg == 16);
            #define G2_BODY(J) do {                                           \
                const float4 ed = sd[(J)];                                    \
                const int c = __float_as_int(ed.w);                           \
                const uint4 v = __ldg(y + (size_t)c * 8 + hl);                \
                const float2 f0 = __half22float2(*(const __half2*)&v.x);      \
                const float2 f1 = __half22float2(*(const __half2*)&v.y);      \
                const float2 f2 = __half22float2(*(const __half2*)&v.z);      \
                ffma2(a0, pk2(ed.x, ed.x), pk2(f0.x, f0.y));                  \
                ffma2(a1, pk2(ed.y, ed.y), pk2(f1.x, f1.y));                  \
                ffma2(a2, pk2(ed.z, ed.z), pk2(f2.x, f2.y));                  \
            } while (0)
            if (u16) {
                #pragma unroll
                for (int j = 0; j < 16; j++) G2_BODY(j);
            } else {
                const int maxd = __reduce_max_sync(0xffffffffu, deg);
                for (int j = 0; j < maxd; j++)
                    if (j < deg) G2_BODY(j);
            }
            #undef G2_BODY
        } else {
            const int maxd = __reduce_max_sync(0xffffffffu, deg);
            for (int j = 0; j < maxd; j++) {
                if (j < deg) {
                    const int e = st + j;
                    const int c = __ldg(col_idx + e);
                    const float2 pv = __ldg(p + e);
                    float g0, g1, g2; GAUSS3(pv, g0, g1, g2);
                    const uint4 v = __ldg(y + (size_t)c * 8 + hl);
                    const float2 f0 = __half22float2(*(const __half2*)&v.x);
                    const float2 f1 = __half22float2(*(const __half2*)&v.y);
                    const float2 f2 = __half22float2(*(const __half2*)&v.z);
                    ffma2(a0, pk2(g0, g0), pk2(f0.x, f0.y));
                    ffma2(a1, pk2(g1, g1), pk2(f1.x, f1.y));
                    ffma2(a2, pk2(g2, g2), pk2(f2.x, f2.y));
                }
            }
        }

        if (valid) {
            float x0, x1, y0v, y1v, z0, z1;
            upk2(a0, x0, x1); upk2(a1, y0v, y1v); upk2(a2, z0, z1);
            float2 o = make_float2(x0 + y0v + z0, x1 + y1v + z1);
            *(float2*)(out + (size_t)n * 16 + 2 * hl) = o;
        }
    }
}

// =============================== launch ====================================
extern "C" void kernel_launch(void* const* d_in, const int* in_sizes, int n_in,
                              void* d_out, int out_size)
{
    const int*    row_ptr = (const int*)d_in[0];    // int32 (JAX x64 disabled)
    const int*    col_idx = (const int*)d_in[1];
    const float*  x       = (const float*)d_in[2];
    const float2* p       = (const float2*)d_in[3];
    const float*  mu      = (const float*)d_in[4];
    const float*  sg      = (const float*)d_in[5];
    const float*  W1      = (const float*)d_in[6];
    const float*  W2      = (const float*)d_in[7];

    const int n_nodes = in_sizes[0] - 1;

    void *y1p, *y2p;
    cudaGetSymbolAddress(&y1p, g_y1);
    cudaGetSymbolAddress(&y2p, g_y2);

    constexpr int NWARP = 8;
    constexpr int GRP   = 8;
    const int gblocks = (n_nodes + NWARP * GRP - 1) / (NWARP * GRP);
    const int tblocks = (n_nodes + 63) / 64;

    // T1: y1 = x * W1  (tensor cores, MT=64, coalesced epilogue)
    t1_mma_kernel<<<tblocks, 256>>>(x, W1, (uint4*)y1p, n_nodes);
    // G1+T2: h = gather(y1) in smem; y2 = h*W2 (padded 128B rows)
    g1t2_kernel<NWARP, GRP><<<gblocks, NWARP * 32>>>(
        row_ptr, col_idx, p, mu, sg, (const uint2*)y1p, W2,
        (unsigned*)y2p, n_nodes);
    // G2: out = gather(y2)  (8 lanes/node, 1x LDG.128/edge)
    gather_h16<NWARP, GRP><<<gblocks, NWARP * 32>>>(
        row_ptr, col_idx, p, mu, sg, (const uint4*)y2p, (float*)d_out, n_nodes);
}